// round 5
// baseline (speedup 1.0000x reference)
#include <cuda_runtime.h>
#include <cuda_bf16.h>
#include <math.h>
#include <stdint.h>

// PhotonicQuantumWalk: B=8, N=2048, C=2, STEPS=64, LOSS_DB=0.1
// sm_100 baseline ISA: HMMA mma.sync + ldmatrix + cp.async.
//
//   conv_split       : fp32 -> exact bf16 hi/lo split (adj, enc_w)
//   gemm_mask_mma    : bf16 3-product HMMA GEMM -> bit-packed maskT + deg
//                      (MMA order: product-major, breaks acc RAW chains)
//   isd_kernel       : inv_sqrt_deg
//   walk_fused       : ALL 64 steps in one persistent kernel,
//                      per-batch device barrier, mask/coin/deg in registers
//   fc_kernel        : probs -> relu fc1 -> fc2

#define BATCH  8
#define NN     2048
#define NWORDS (NN / 32)
#define STEPS  64
#define SBLK   32

// ---------------- device scratch ----------------
__device__ float    g_sA[BATCH * NN * 4];
__device__ float    g_sB[BATCH * NN * 4];
__device__ unsigned g_maskT[BATCH * NN * NWORDS];
__device__ int      g_deg[BATCH * NN];
__device__ float    g_isd[BATCH * NN];
__device__ float    g_partials[2][BATCH][SBLK];
__device__ unsigned g_bar[BATCH];
__device__ __nv_bfloat16 g_adj_hi[(size_t)BATCH * NN * NN];
__device__ __nv_bfloat16 g_adj_lo[(size_t)BATCH * NN * NN];
__device__ __nv_bfloat16 g_w_hi[(size_t)NN * NN];
__device__ __nv_bfloat16 g_w_lo[(size_t)NN * NN];

// ---------------- helpers ----------------
__device__ __forceinline__ uint32_t smem_u32(const void* p) {
    uint32_t a;
    asm("{ .reg .u64 t; cvta.to.shared.u64 t, %1; cvt.u32.u64 %0, t; }"
        : "=r"(a) : "l"(p));
    return a;
}
__device__ __forceinline__ unsigned ld_acquire_gpu(const unsigned* p) {
    unsigned v;
    asm volatile("ld.acquire.gpu.u32 %0, [%1];" : "=r"(v) : "l"(p) : "memory");
    return v;
}

#define LDM4(r, addr) \
    asm volatile("ldmatrix.sync.aligned.m8n8.x4.shared.b16 {%0,%1,%2,%3}, [%4];" \
        : "=r"((r)[0]), "=r"((r)[1]), "=r"((r)[2]), "=r"((r)[3]) : "r"(addr))

#define MMA16816(d, a, b0, b1) \
    asm volatile("mma.sync.aligned.m16n8k16.row.col.f32.bf16.bf16.f32 " \
        "{%0,%1,%2,%3}, {%4,%5,%6,%7}, {%8,%9}, {%0,%1,%2,%3};" \
        : "+f"((d)[0]), "+f"((d)[1]), "+f"((d)[2]), "+f"((d)[3]) \
        : "r"((a)[0]), "r"((a)[1]), "r"((a)[2]), "r"((a)[3]), "r"(b0), "r"(b1))

#define CP_ASYNC16(dst, src) \
    asm volatile("cp.async.cg.shared.global [%0], [%1], 16;" :: "r"(dst), "l"(src))
#define CP_COMMIT() asm volatile("cp.async.commit_group;" ::: "memory")
#define CP_WAIT(n)  asm volatile("cp.async.wait_group %0;" :: "n"(n) : "memory")

// ---------------- init ----------------
__global__ void init_kernel() {
    int i = blockIdx.x * blockDim.x + threadIdx.x;
    if (i < BATCH * NN * 4) g_sA[i] = 0.015625f;   // 1/sqrt(N*C)
    if (i < BATCH * NN)     g_deg[i] = 0;
    if (i < BATCH)          g_bar[i] = 0;
}

// ---------------- fp32 -> bf16 hi/lo split ----------------
__global__ void conv_split_kernel(const float* __restrict__ src,
                                  __nv_bfloat16* __restrict__ hi,
                                  __nv_bfloat16* __restrict__ lo, size_t n4) {
    size_t i = (size_t)blockIdx.x * blockDim.x + threadIdx.x;
    if (i >= n4) return;
    float4 v = ((const float4*)src)[i];
    __nv_bfloat16 h0 = __float2bfloat16(v.x);
    __nv_bfloat16 h1 = __float2bfloat16(v.y);
    __nv_bfloat16 h2 = __float2bfloat16(v.z);
    __nv_bfloat16 h3 = __float2bfloat16(v.w);
    __nv_bfloat16 l0 = __float2bfloat16(v.x - __bfloat162float(h0));
    __nv_bfloat16 l1 = __float2bfloat16(v.y - __bfloat162float(h1));
    __nv_bfloat16 l2 = __float2bfloat16(v.z - __bfloat162float(h2));
    __nv_bfloat16 l3 = __float2bfloat16(v.w - __bfloat162float(h3));
    __nv_bfloat162* H = (__nv_bfloat162*)hi;
    __nv_bfloat162* L = (__nv_bfloat162*)lo;
    H[2 * i]     = __nv_bfloat162(h0, h1);
    H[2 * i + 1] = __nv_bfloat162(h2, h3);
    L[2 * i]     = __nv_bfloat162(l0, l1);
    L[2 * i + 1] = __nv_bfloat162(l2, l3);
}

// ---------------- HMMA GEMM + mask extraction ----------------
#define BK       32
#define GCHUNKS  (NN / BK)
#define TILE_B   8192
#define STAGE_B  (4 * TILE_B)
#define GSTAGES  3

#define LOAD_CHUNK(cc, stg) do {                                               \
    uint32_t dstb = smb + (stg) * STAGE_B;                                     \
    int kt = (cc) * BK;                                                        \
    _Pragma("unroll")                                                          \
    for (int it = 0; it < 8; it++) {                                           \
        int arr = it >> 1;                                                     \
        int rem = ((it & 1) << 8) + tid;                                       \
        int row = rem >> 2;                                                    \
        int ch  = rem & 3;                                                     \
        int gr  = ((arr < 2) ? n0 : j0) + row;                                 \
        const __nv_bfloat16* src = srcs[arr] + (size_t)gr * NN + kt + ch * 8;  \
        uint32_t dst = dstb + arr * TILE_B + row * 64 +                        \
                       (((ch ^ ((row >> 1) & 3))) << 4);                       \
        CP_ASYNC16(dst, src);                                                  \
    }                                                                          \
    CP_COMMIT();                                                               \
} while (0)

__global__ void __launch_bounds__(256, 2) gemm_mask_mma(const float* __restrict__ bias) {
    extern __shared__ __align__(1024) char sm[];
    __shared__ float sbias[128];

    int tid  = threadIdx.x;
    int lane = tid & 31;
    int wid  = tid >> 5;
    int b  = blockIdx.z;
    int j0 = blockIdx.x * 128;
    int n0 = blockIdx.y * 128;

    const __nv_bfloat16* srcs[4] = {
        g_adj_hi + (size_t)b * NN * NN, g_adj_lo + (size_t)b * NN * NN,
        g_w_hi, g_w_lo };

    if (tid < 128) sbias[tid] = bias[j0 + tid];

    uint32_t smb = smem_u32(sm);

    LOAD_CHUNK(0, 0);
    LOAD_CHUNK(1, 1);

    int warp_m = (wid & 1) * 64;
    int warp_j = (wid >> 1) * 32;
    int lrow   = lane & 15;
    int lhalf  = lane >> 4;

    float acc[4][4][4];
#pragma unroll
    for (int mt = 0; mt < 4; mt++)
#pragma unroll
        for (int jt = 0; jt < 4; jt++)
#pragma unroll
            for (int q = 0; q < 4; q++) acc[mt][jt][q] = 0.f;

    for (int c = 0; c < GCHUNKS; c++) {
        if (c + GSTAGES - 1 < GCHUNKS)
            LOAD_CHUNK(c + GSTAGES - 1, (c + GSTAGES - 1) % GSTAGES);
        CP_WAIT(GSTAGES - 1);
        __syncthreads();

        uint32_t sbase = smb + (c % GSTAGES) * STAGE_B;
#pragma unroll
        for (int k16 = 0; k16 < 2; k16++) {
            int chunkid = k16 * 2 + lhalf;
            uint32_t bf[2][2][4];
#pragma unroll
            for (int part = 0; part < 2; part++)
#pragma unroll
                for (int jt2 = 0; jt2 < 2; jt2++) {
                    int row = warp_j + jt2 * 16 + lrow;
                    uint32_t addr = sbase + (2 + part) * TILE_B + row * 64 +
                                    ((chunkid ^ ((row >> 1) & 3)) << 4);
                    LDM4(bf[part][jt2], addr);
                }
            uint32_t am[4][4];
#pragma unroll
            for (int mt = 0; mt < 4; mt++) {
                int row = warp_m + mt * 16 + lrow;
                LDM4(am[mt], sbase + row * 64 + ((chunkid ^ ((row >> 1) & 3)) << 4));
            }
            // product-major MMA sweeps: same-acc MMAs are 16 apart
#pragma unroll
            for (int mt = 0; mt < 4; mt++)
#pragma unroll
                for (int jt = 0; jt < 4; jt++) {
                    int g = jt >> 1, o = jt & 1;
                    MMA16816(acc[mt][jt], am[mt], bf[0][g][o], bf[0][g][o + 2]);
                }
#pragma unroll
            for (int mt = 0; mt < 4; mt++)
#pragma unroll
                for (int jt = 0; jt < 4; jt++) {
                    int g = jt >> 1, o = jt & 1;
                    MMA16816(acc[mt][jt], am[mt], bf[1][g][o], bf[1][g][o + 2]);
                }
#pragma unroll
            for (int mt = 0; mt < 4; mt++) {
                int row = warp_m + mt * 16 + lrow;
                LDM4(am[mt], sbase + TILE_B + row * 64 +
                             ((chunkid ^ ((row >> 1) & 3)) << 4));
            }
#pragma unroll
            for (int mt = 0; mt < 4; mt++)
#pragma unroll
                for (int jt = 0; jt < 4; jt++) {
                    int g = jt >> 1, o = jt & 1;
                    MMA16816(acc[mt][jt], am[mt], bf[0][g][o], bf[0][g][o + 2]);
                }
        }
        __syncthreads();
    }

    CP_WAIT(0);
    __syncthreads();

    unsigned char* sgn = (unsigned char*)sm;
#pragma unroll
    for (int mt = 0; mt < 4; mt++)
#pragma unroll
        for (int jt = 0; jt < 4; jt++) {
            int r0 = warp_m + mt * 16 + (lane >> 2);
            int jc = warp_j + jt * 8 + (lane & 3) * 2;
            float z00 = acc[mt][jt][0] + sbias[jc];
            float z01 = acc[mt][jt][1] + sbias[jc + 1];
            float z10 = acc[mt][jt][2] + sbias[jc];
            float z11 = acc[mt][jt][3] + sbias[jc + 1];
            sgn[r0 * 128 + jc]           = (z00 > 0.f) ? 1 : 0;
            sgn[r0 * 128 + jc + 1]       = (z01 > 0.f) ? 1 : 0;
            sgn[(r0 + 8) * 128 + jc]     = (z10 > 0.f) ? 1 : 0;
            sgn[(r0 + 8) * 128 + jc + 1] = (z11 > 0.f) ? 1 : 0;
        }
    __syncthreads();

    for (int idx = tid; idx < 512; idx += 256) {
        int jl = idx >> 2;
        int w  = idx & 3;
        unsigned word = 0;
#pragma unroll
        for (int i = 0; i < 32; i++)
            word |= ((unsigned)sgn[(w * 32 + i) * 128 + jl]) << i;
        g_maskT[((size_t)b * NN + j0 + jl) * NWORDS + (n0 >> 5) + w] = word;
    }
    if (tid < 128) {
        int s = 0;
#pragma unroll 16
        for (int j = 0; j < 128; j++) s += sgn[tid * 128 + j];
        atomicAdd(&g_deg[b * NN + n0 + tid], s);
    }
}

// ---------------- inv_sqrt_deg ----------------
__global__ void isd_kernel() {
    int i = blockIdx.x * blockDim.x + threadIdx.x;
    if (i < BATCH * NN) {
        int d = g_deg[i];
        g_isd[i] = (d > 0) ? (1.0f / sqrtf((float)d)) : 0.0f;
    }
}

// ---------------- fused 64-step walk ----------------
// Grid (SBLK=32, BATCH=8) = 256 blocks x 512 thr; __launch_bounds__(512,2)
// guarantees 2 CTA/SM -> 296 wave-1 slots >= 256 (spin-barrier safe).
// Per-batch device barrier: 32 arrivals per step.
__global__ void __launch_bounds__(512, 2) walk_fused(const float* __restrict__ coin) {
    __shared__ float4 amp[NN];       // 32 KB
    __shared__ float  warpsum[16];
    __shared__ float  s_scale;

    int b    = blockIdx.y;
    int tid  = threadIdx.x;
    int lane = tid & 31;
    int wid  = tid >> 5;
    int m0   = blockIdx.x * 64 + wid * 4;

    // Frobenius-normalized coin (persistent registers)
    float c[8];
    float cn = 0.f;
#pragma unroll
    for (int i = 0; i < 8; i++) { c[i] = coin[i]; cn += c[i] * c[i]; }
    float cinv = rsqrtf(cn);
#pragma unroll
    for (int i = 0; i < 8; i++) c[i] *= cinv;

    // persistent mask words + degree flags
    unsigned mw[2][4];
    int isod[4];
#pragma unroll
    for (int r = 0; r < 4; r++) {
        const unsigned* basep = &g_maskT[((size_t)b * NN + m0 + r) * NWORDS];
        mw[0][r] = basep[lane];
        mw[1][r] = basep[32 + lane];
        isod[r] = g_deg[b * NN + m0 + r];
    }
    unsigned lanebit = 1u << lane;

    for (int t = 0; t < STEPS; t++) {
        const float4* s_in  = (const float4*)((t & 1) ? g_sB : g_sA);
        float4*       s_out = (float4*)((t & 1) ? g_sA : g_sB);
        float lf = expf(-0.01f * (float)t);

        // scale = 1/(||s_{t-1}||+1e-8), computed by warp 0, broadcast via smem
        if (wid == 0) {
            float v = 0.f;
            if (t > 0) v = __ldcg(&g_partials[(t - 1) & 1][b][lane]);
#pragma unroll
            for (int off = 16; off > 0; off >>= 1)
                v += __shfl_xor_sync(0xffffffffu, v, off);
            if (lane == 0)
                s_scale = (t > 0) ? (1.0f / (sqrtf(v) + 1e-8f)) : 1.0f;
        }
        __syncthreads();
        float scale = s_scale;

        // amp[n] = (coin_norm @ s)[n] * isd[n] * scale
        for (int n = tid; n < NN; n += 512) {
            float4 s = __ldcg(&s_in[b * NN + n]);
            float e0r = c[0] * s.x - c[1] * s.y + c[2] * s.z - c[3] * s.w;
            float e0i = c[0] * s.y + c[1] * s.x + c[2] * s.w + c[3] * s.z;
            float e1r = c[4] * s.x - c[5] * s.y + c[6] * s.z - c[7] * s.w;
            float e1i = c[4] * s.y + c[5] * s.x + c[6] * s.w + c[7] * s.z;
            float f = g_isd[b * NN + n] * scale;
            amp[n] = make_float4(e0r * f, e0i * f, e1r * f, e1i * f);
        }
        __syncthreads();

        unsigned long long a0[4], a1[4];
#pragma unroll
        for (int r = 0; r < 4; r++) { a0[r] = 0ull; a1[r] = 0ull; }

#pragma unroll
        for (int h = 0; h < 2; h++) {
#pragma unroll 8
            for (int w2 = 0; w2 < 32; w2++) {
                int n = ((h << 5) + w2) * 32 + lane;
                ulonglong2 v = *reinterpret_cast<const ulonglong2*>(&amp[n]);
#pragma unroll
                for (int r = 0; r < 4; r++) {
                    unsigned word = __shfl_sync(0xffffffffu, mw[h][r], w2);
                    unsigned bit = word & lanebit;
                    asm volatile(
                        "{\n\t.reg .pred p;\n\t"
                        "setp.ne.u32 p, %4, 0;\n\t"
                        "@p add.rn.f32x2 %0, %0, %2;\n\t"
                        "@p add.rn.f32x2 %1, %1, %3;\n\t}"
                        : "+l"(a0[r]), "+l"(a1[r])
                        : "l"(v.x), "l"(v.y), "r"(bit));
                }
            }
        }

        float local = 0.f;
#pragma unroll
        for (int r = 0; r < 4; r++) {
            float ax = __uint_as_float((unsigned)a0[r]);
            float ay = __uint_as_float((unsigned)(a0[r] >> 32));
            float az = __uint_as_float((unsigned)a1[r]);
            float aw = __uint_as_float((unsigned)(a1[r] >> 32));
#pragma unroll
            for (int off = 16; off > 0; off >>= 1) {
                ax += __shfl_xor_sync(0xffffffffu, ax, off);
                ay += __shfl_xor_sync(0xffffffffu, ay, off);
                az += __shfl_xor_sync(0xffffffffu, az, off);
                aw += __shfl_xor_sync(0xffffffffu, aw, off);
            }
            if (lane == 0) {
                int m = m0 + r;
                if (isod[r] == 0) {
                    float4 s = __ldcg(&s_in[b * NN + m]);
                    ax = (c[0] * s.x - c[1] * s.y + c[2] * s.z - c[3] * s.w) * scale;
                    ay = (c[0] * s.y + c[1] * s.x + c[2] * s.w + c[3] * s.z) * scale;
                    az = (c[4] * s.x - c[5] * s.y + c[6] * s.z - c[7] * s.w) * scale;
                    aw = (c[4] * s.y + c[5] * s.x + c[6] * s.w + c[7] * s.z) * scale;
                }
                ax *= lf; ay *= lf; az *= lf; aw *= lf;
                s_out[b * NN + m] = make_float4(ax, ay, az, aw);
                local += ax * ax + ay * ay + az * az + aw * aw;
            }
        }
        if (lane == 0) warpsum[wid] = local;
        __syncthreads();
        if (tid == 0) {
            float ts = 0.f;
#pragma unroll
            for (int i = 0; i < 16; i++) ts += warpsum[i];
            g_partials[t & 1][b][blockIdx.x] = ts;
            __threadfence();
            atomicAdd(&g_bar[b], 1u);
            if (t < STEPS - 1) {
                unsigned target = (unsigned)(SBLK * (t + 1));
                while (ld_acquire_gpu(&g_bar[b]) < target) __nanosleep(64);
            }
        }
        __syncthreads();
    }
}

// ---------------- final probs + 2-layer MLP ----------------
__global__ void __launch_bounds__(128) fc_kernel(
    const float* __restrict__ f1w, const float* __restrict__ f1b,
    const float* __restrict__ f2w, const float* __restrict__ f2b,
    float* __restrict__ out) {
    __shared__ __align__(16) float probs[NN * 2];
    __shared__ float h[128];
    int b = blockIdx.x, tid = threadIdx.x;

    const float* p = g_partials[(STEPS - 1) & 1][b];
    float t = 0.f;
#pragma unroll
    for (int i = 0; i < SBLK; i++) t += p[i];
    float dd = sqrtf(t) + 1e-8f;
    float sc = 1.0f / (dd * dd);

    const float4* s = (const float4*)g_sA;
    for (int n = tid; n < NN; n += 128) {
        float4 v = s[b * NN + n];
        probs[2 * n]     = (v.x * v.x + v.y * v.y) * sc;
        probs[2 * n + 1] = (v.z * v.z + v.w * v.w) * sc;
    }
    __syncthreads();

    {
        int j = tid;
        float acc = f1b[j];
        const float4* w4 = (const float4*)(f1w + (size_t)j * NN * 2);
        const float4* p4 = (const float4*)probs;
#pragma unroll 4
        for (int i = 0; i < NN * 2 / 4; i++) {
            float4 w = w4[i];
            float4 q = p4[i];
            acc += w.x * q.x + w.y * q.y + w.z * q.z + w.w * q.w;
        }
        h[j] = fmaxf(acc, 0.f);
    }
    __syncthreads();
    if (tid < 64) {
        float acc = f2b[tid];
#pragma unroll 8
        for (int j = 0; j < 128; j++) acc += h[j] * f2w[tid * 128 + j];
        out[b * 64 + tid] = acc;
    }
}

// ---------------- launch ----------------
extern "C" void kernel_launch(void* const* d_in, const int* in_sizes, int n_in,
                              void* d_out, int out_size) {
    const float* adj  = (const float*)d_in[0];
    const float* coin = (const float*)d_in[1];
    const float* encw = (const float*)d_in[2];
    const float* encb = (const float*)d_in[3];
    const float* f1w  = (const float*)d_in[4];
    const float* f1b  = (const float*)d_in[5];
    const float* f2w  = (const float*)d_in[6];
    const float* f2b  = (const float*)d_in[7];
    float* out = (float*)d_out;

    cudaFuncSetAttribute(gemm_mask_mma,
                         cudaFuncAttributeMaxDynamicSharedMemorySize,
                         GSTAGES * STAGE_B);

    init_kernel<<<(BATCH * NN * 4 + 255) / 256, 256>>>();

    {
        __nv_bfloat16 *ahi, *alo, *whi, *wlo;
        cudaGetSymbolAddress((void**)&ahi, g_adj_hi);
        cudaGetSymbolAddress((void**)&alo, g_adj_lo);
        cudaGetSymbolAddress((void**)&whi, g_w_hi);
        cudaGetSymbolAddress((void**)&wlo, g_w_lo);
        size_t n4a = (size_t)BATCH * NN * NN / 4;
        size_t n4w = (size_t)NN * NN / 4;
        conv_split_kernel<<<(unsigned)((n4a + 255) / 256), 256>>>(adj, ahi, alo, n4a);
        conv_split_kernel<<<(unsigned)((n4w + 255) / 256), 256>>>(encw, whi, wlo, n4w);
    }

    gemm_mask_mma<<<dim3(NN / 128, NN / 128, BATCH), 256, GSTAGES * STAGE_B>>>(encb);

    isd_kernel<<<(BATCH * NN + 255) / 256, 256>>>();

    walk_fused<<<dim3(SBLK, BATCH), 512>>>(coin);

    fc_kernel<<<BATCH, 128>>>(f1w, f1b, f2w, f2b, out);
}